// round 14
// baseline (speedup 1.0000x reference)
#include <cuda_runtime.h>
#include <math_constants.h>

#define NB 4
#define NN 16384
#define NM 512
#define NC 128
#define NK 16
#define NL 6
#define NSTEPS 5

// ---------------- scratch (device globals: no allocations allowed) ----------
__device__ float g_feats[NB*NN*NC];
__device__ float g_Qf[NB*NN*NC];
__device__ float g_Gf[NB*NN*NC];
__device__ __align__(16) float g_pos4[NB*NN*4];
__device__ float g_wsel[NB*NM*NL*NC];
__device__ float g_rout[2][NB*NM*NL*NC];
__device__ float g_disp[NB*NM*3];
// transposed weights WT[mat][j][c]; mat: 0 wq, 1 wk, 2 wv, 3 w_out, 4 rt_w1,
// 5 rt_w2, 6 beta, 7 gamma
__device__ __align__(16) float g_WT[8*128*128];

// ---------------- f32x2 packed helpers --------------------------------------
__device__ __forceinline__ void dfma2(unsigned long long& d,
                                      unsigned long long a,
                                      unsigned long long b) {
    asm("fma.rn.f32x2 %0, %1, %2, %0;" : "+l"(d) : "l"(a), "l"(b));
}
__device__ __forceinline__ unsigned long long dadd2(unsigned long long a,
                                                    unsigned long long b) {
    unsigned long long r;
    asm("add.rn.f32x2 %0, %1, %2;" : "=l"(r) : "l"(a), "l"(b));
    return r;
}
__device__ __forceinline__ unsigned long long dmul2(unsigned long long a,
                                                    unsigned long long b) {
    unsigned long long r;
    asm("mul.rn.f32x2 %0, %1, %2;" : "=l"(r) : "l"(a), "l"(b));
    return r;
}
__device__ __forceinline__ unsigned long long dfmar2(unsigned long long a,
                                                     unsigned long long b,
                                                     unsigned long long c) {
    unsigned long long r;
    asm("fma.rn.f32x2 %0, %1, %2, %3;" : "=l"(r) : "l"(a), "l"(b), "l"(c));
    return r;
}
__device__ __forceinline__ unsigned long long packdup(float w) {
    unsigned long long r;
    asm("mov.b64 %0, {%1, %1};" : "=l"(r) : "f"(w));
    return r;
}
__device__ __forceinline__ void unpack2(unsigned long long a, float& lo, float& hi) {
    asm("mov.b64 {%0, %1}, %2;" : "=f"(lo), "=f"(hi) : "l"(a));
}

// ---------------- one-time weight transpose ---------------------------------
__global__ void transpose_kernel(const float* __restrict__ w_in,
                                 const float* __restrict__ w_out,
                                 const float* __restrict__ rt_w1,
                                 const float* __restrict__ rt_w2,
                                 const float* __restrict__ bw,
                                 const float* __restrict__ gw) {
    int gid = blockIdx.x * 256 + threadIdx.x;   // 131072 threads
    int mat = gid >> 14, rem = gid & 16383;
    int j = rem >> 7, c = rem & 127;
    const float* src;
    switch (mat) {
        case 0: src = w_in;          break;
        case 1: src = w_in + 16384;  break;
        case 2: src = w_in + 32768;  break;
        case 3: src = w_out;         break;
        case 4: src = rt_w1;         break;
        case 5: src = rt_w2;         break;
        case 6: src = bw;            break;
        default: src = gw;           break;
    }
    g_WT[gid] = src[c*128 + j];
}

// ---------------- fused init + encoder --------------------------------------
__global__ void init_encode_kernel(const float* __restrict__ xyz,
                                   const float* __restrict__ w1, const float* __restrict__ b1,
                                   const float* __restrict__ w2, const float* __restrict__ b2) {
    __shared__ float h[4][64];
    int tid = threadIdx.x;
    int p0 = blockIdx.x * 4;
    if (tid < 4) {
        const float* x = xyz + (size_t)(p0 + tid) * 3;
        *(float4*)&g_pos4[(size_t)(p0 + tid)*4] = make_float4(x[0], x[1], x[2], 0.f);
    }
    for (int i = tid; i < 4*64; i += 128) {
        int pt = i >> 6, j = i & 63;
        const float* x = xyz + (size_t)(p0 + pt) * 3;
        float v = b1[j] + w1[j*3+0]*x[0] + w1[j*3+1]*x[1] + w1[j*3+2]*x[2];
        h[pt][j] = fmaxf(v, 0.f);
    }
    __syncthreads();
    float acc[4];
    #pragma unroll
    for (int p = 0; p < 4; p++) acc[p] = b2[tid];
    const float4* wr = (const float4*)(w2 + (size_t)tid * 64);
    #pragma unroll
    for (int j4 = 0; j4 < 16; j4++) {
        float4 w = wr[j4];
        #pragma unroll
        for (int p = 0; p < 4; p++) {
            float4 hv = *(const float4*)&h[p][4*j4];
            acc[p] += w.x*hv.x + w.y*hv.y + w.z*hv.z + w.w*hv.w;
        }
    }
    #pragma unroll
    for (int p = 0; p < 4; p++)
        g_feats[(size_t)(p0 + p) * NC + tid] = acc[p];
}

// ---------------- beta/gamma projections (transposed weights, coalesced) ----
__global__ void proj_kernel(const float* __restrict__ bb, const float* __restrict__ gb) {
    __shared__ __align__(8) float xs[128*16];      // xs[j*16 + p]
    int c = threadIdx.x;                           // 128 threads
    size_t base = (size_t)blockIdx.x * 16 * 128;
    for (int i = c; i < 16*128; i += 128) {
        int p = i >> 7, ch = i & 127;
        xs[ch*16 + p] = g_feats[base + i];
    }
    __syncthreads();
    unsigned long long accQ[8], accG[8];
    unsigned long long bq = packdup(bb[c]), bg = packdup(gb[c]);
    #pragma unroll
    for (int p = 0; p < 8; p++) { accQ[p] = bq; accG[p] = bg; }
    const float* WTb = g_WT + 6*16384;
    const float* WTg = g_WT + 7*16384;
    #pragma unroll 4
    for (int j = 0; j < 128; j++) {
        unsigned long long wa  = packdup(__ldg(WTb + j*128 + c));
        unsigned long long wgv = packdup(__ldg(WTg + j*128 + c));
        const unsigned long long* x2 = (const unsigned long long*)&xs[j*16];
        #pragma unroll
        for (int p = 0; p < 8; p++) {
            dfma2(accQ[p], x2[p], wa);
            dfma2(accG[p], x2[p], wgv);
        }
    }
    #pragma unroll
    for (int p = 0; p < 8; p++) {
        float q0, q1, g0, g1;
        unpack2(accQ[p], q0, q1);
        unpack2(accG[p], g0, g1);
        g_Qf[base + (size_t)(2*p)*128 + c]   = q0;
        g_Qf[base + (size_t)(2*p+1)*128 + c] = q1;
        g_Gf[base + (size_t)(2*p)*128 + c]   = g0;
        g_Gf[base + (size_t)(2*p+1)*128 + c] = g1;
    }
}

// ---------------- KNN: warp-distributed sorted top-17 insert ----------------
__device__ __forceinline__ void kinsert(unsigned bal, float d, int ci,
                                        float& ld, int& li, float& tau, int lane) {
    do {
        int src = __ffs(bal) - 1; bal &= bal - 1;
        float dc = __shfl_sync(0xffffffffu, d, src);
        int   ic = __shfl_sync(0xffffffffu, ci, src);
        float pd = __shfl_up_sync(0xffffffffu, ld, 1);
        int   pi = __shfl_up_sync(0xffffffffu, li, 1);
        unsigned lt = __ballot_sync(0xffffffffu,
                (ld < dc) || ((ld == dc) && (li < ic))) & 0x1FFFFu;
        int pn = __popc(lt);
        if (lane < 17) {
            if (lane == pn)      { ld = dc; li = ic; }
            else if (lane > pn)  { ld = pd; li = pi; }
        }
    } while (bal);
    tau = __shfl_sync(0xffffffffu, ld, 16);
}

// ---------------- fused per-step selector, positions resident in smem ------
#define KTPB 512
#define KQPB 16
#define KNN_SMEM (3*NN*4)

__global__ __launch_bounds__(KTPB)
void knn_step_kernel(const int* __restrict__ start,
                     const float* __restrict__ gumbel, int t) {
    extern __shared__ __align__(8) float sm[];
    float* sx = sm;
    float* sy = sm + NN;
    float* sz = sm + 2*NN;
    int tid = threadIdx.x, warp = tid >> 5, lane = tid & 31;
    int b = blockIdx.x / (NM/KQPB);             // 32 blocks per batch
    int m = (blockIdx.x % (NM/KQPB)) * KQPB + warp;
    int gw = b*NM + m;
    int qidx = start[gw];
    const float4* pos = (const float4*)(g_pos4 + (size_t)b*NN*4);
    const float* Gf = g_Gf + (size_t)b*NN*NC;

    for (int i = tid; i < NN; i += KTPB) {
        float4 p = pos[i];
        sx[i] = p.x; sy[i] = p.y; sz[i] = p.z;
    }
    {   // walk[0] = feats[start]
        const float* fr = g_feats + ((size_t)b*NN + qidx) * NC;
        float* wr = g_wsel + (size_t)gw * NL * NC;
        #pragma unroll
        for (int r = 0; r < 4; r++) wr[lane + 32*r] = fr[lane + 32*r];
    }
    __syncthreads();

    const unsigned long long* sx2 = (const unsigned long long*)sx;
    const unsigned long long* sy2 = (const unsigned long long*)sy;
    const unsigned long long* sz2 = (const unsigned long long*)sz;

    for (int l = 0; l < NL-1; l++) {
        float qx = sx[qidx], qy = sy[qidx], qz = sz[qidx];
        unsigned long long nqx = packdup(-qx);
        unsigned long long nqy = packdup(-qy);
        unsigned long long nqz = packdup(-qz);
        float ld = CUDART_INF_F;
        int   li = 0x7FFFFFFF;
        float tau = CUDART_INF_F;

        for (int pi = lane; pi < NN/2; pi += 32) {
            unsigned long long dxp = dadd2(sx2[pi], nqx);
            unsigned long long dyp = dadd2(sy2[pi], nqy);
            unsigned long long dzp = dadd2(sz2[pi], nqz);
            unsigned long long dp = dmul2(dxp, dxp);
            dp = dfmar2(dyp, dyp, dp);
            dp = dfmar2(dzp, dzp, dp);       // dz*dz + (dy*dy + dx*dx), per-lane IEEE
            float d0, d1;
            unpack2(dp, d0, d1);
            int c0 = 2*pi;
            unsigned bal0 = __ballot_sync(0xffffffffu, d0 < tau);
            if (bal0) kinsert(bal0, d0, c0, ld, li, tau, lane);
            unsigned bal1 = __ballot_sync(0xffffffffu, d1 < tau);
            if (bal1) kinsert(bal1, d1, c0 + 1, ld, li, tau, lane);
        }

        int nb = __shfl_sync(0xffffffffu, li, lane < 31 ? lane + 1 : 31);
        const float* Q = g_Qf + ((size_t)b*NN + qidx) * NC;
        float qv0 = Q[lane], qv1 = Q[lane+32], qv2 = Q[lane+64], qv3 = Q[lane+96];
        float pk[16];
        #pragma unroll
        for (int k = 0; k < 16; k++) {
            int nk = __shfl_sync(0xffffffffu, nb, k);   // li of lane k+1
            const float* gr = Gf + (size_t)nk * NC;
            pk[k] = qv0*gr[lane] + qv1*gr[lane+32] + qv2*gr[lane+64] + qv3*gr[lane+96];
        }
        #pragma unroll
        for (int k = 0; k < 16; k++) {
            #pragma unroll
            for (int off = 16; off; off >>= 1)
                pk[k] += __shfl_xor_sync(0xffffffffu, pk[k], off);
        }
        const float* gm = gumbel + ((((size_t)t*(NL-1) + l)*NB + b)*NM + m) * NK;
        float best = -CUDART_INF_F; int bk = 0;
        #pragma unroll
        for (int k = 0; k < 16; k++) {
            float s = pk[k] / 11.313708498984761f + gm[k];   // /sqrt(128)
            if (s > best) { best = s; bk = k; }
        }
        qidx = __shfl_sync(0xffffffffu, li, bk + 1);
        const float* fr = g_feats + ((size_t)b*NN + qidx) * NC;
        float* wr = g_wsel + ((size_t)gw * NL + (l + 1)) * NC;
        #pragma unroll
        for (int r = 0; r < 4; r++) wr[lane + 32*r] = fr[lane + 32*r];
    }
}

// ---------------- route matmul: transposed weights, coalesced LDG.64 --------
// thread t computes channels c0=2t, c1=2t+1 for both sequences.
__device__ __forceinline__ void mm64t(const float (*in)[128][2],
                                      const float* __restrict__ WT,
                                      const float* __restrict__ bias,
                                      float (*out)[128][2],
                                      int t, bool doRelu) {
    int c0 = 2*t;
    unsigned long long acc0[6], acc1[6];
    unsigned long long b0 = packdup(bias[c0]), b1 = packdup(bias[c0 + 1]);
    #pragma unroll
    for (int i = 0; i < 6; i++) { acc0[i] = b0; acc1[i] = b1; }
    const unsigned long long* inu = (const unsigned long long*)in;
    const float2* wt2 = (const float2*)(WT + c0);   // row j at wt2[j*64]
    #pragma unroll 4
    for (int j = 0; j < 128; j++) {
        float2 w = __ldg(&wt2[j*64]);
        unsigned long long w0 = packdup(w.x), w1 = packdup(w.y);
        #pragma unroll
        for (int l2 = 0; l2 < 6; l2++) {
            unsigned long long r = inu[l2*128 + j];
            dfma2(acc0[l2], r, w0);
            dfma2(acc1[l2], r, w1);
        }
    }
    #pragma unroll
    for (int l2 = 0; l2 < 6; l2++) {
        float v0, v1, u0, u1;
        unpack2(acc0[l2], v0, v1);
        unpack2(acc1[l2], u0, u1);
        if (doRelu) {
            v0 = fmaxf(v0, 0.f); v1 = fmaxf(v1, 0.f);
            u0 = fmaxf(u0, 0.f); u1 = fmaxf(u1, 0.f);
        }
        out[l2][c0][0] = v0;     out[l2][c0][1] = v1;
        out[l2][c0+1][0] = u0;   out[l2][c0+1][1] = u1;
    }
}

__global__ void route_kernel(const float* __restrict__ b_in,
                             const float* __restrict__ b_out,
                             const float* __restrict__ rt_b1,
                             const float* __restrict__ rt_b2,
                             const float* __restrict__ pw1, const float* __restrict__ pb1,
                             const float* __restrict__ pw2, const float* __restrict__ pb2,
                             int curBuf, int prevBuf) {
    __shared__ __align__(16) float xin[6][128][2];
    __shared__ __align__(16) float pin[6][128][2];
    __shared__ __align__(16) float qs[6][128][2];
    __shared__ __align__(16) float ks[6][128][2];
    __shared__ __align__(16) float vs[6][128][2];
    __shared__ float sc[2][4][6][6];
    int tid = threadIdx.x;                      // 64 threads
    size_t seq0 = (size_t)blockIdx.x * 2;
    const float* curr = g_wsel;
    const float* prev = (prevBuf < 0) ? g_wsel : g_rout[prevBuf];
    for (int i = tid; i < 2*6*128; i += 64) {
        int s = i / 768, r = i % 768;
        ((float*)xin)[r*2 + s] = curr[(seq0 + s)*768 + r];
        ((float*)pin)[r*2 + s] = prev[(seq0 + s)*768 + r];
    }
    __syncthreads();
    mm64t(xin, g_WT,             b_in,        qs, tid, false);   // wq
    mm64t(pin, g_WT + 16384,     b_in + 128,  ks, tid, false);   // wk
    mm64t(pin, g_WT + 2*16384,   b_in + 256,  vs, tid, false);   // wv
    __syncthreads();
    int warp = tid >> 5, lane = tid & 31;
    for (int pp = warp; pp < 8; pp += 2) {
        int s = pp >> 2, h = pp & 3;
        for (int e = lane; e < 36; e += 32) {
            int lq = e / 6, lk = e % 6;
            float d = 0.f;
            #pragma unroll
            for (int dd = 0; dd < 32; dd++)
                d += qs[lq][h*32 + dd][s] * ks[lk][h*32 + dd][s];
            sc[s][h][lq][lk] = d / 5.656854249492381f;
        }
        __syncwarp();
        if (lane < 6) {
            float mx = -CUDART_INF_F;
            #pragma unroll
            for (int j = 0; j < 6; j++) mx = fmaxf(mx, sc[s][h][lane][j]);
            float ex[6]; float sum = 0.f;
            #pragma unroll
            for (int j = 0; j < 6; j++) { ex[j] = expf(sc[s][h][lane][j] - mx); sum += ex[j]; }
            #pragma unroll
            for (int j = 0; j < 6; j++) sc[s][h][lane][j] = ex[j] / sum;
        }
        __syncwarp();
        for (int lq = 0; lq < 6; lq++) {
            float o = 0.f;
            #pragma unroll
            for (int j = 0; j < 6; j++) o += sc[s][h][lq][j] * vs[j][h*32 + lane][s];
            xin[lq][h*32 + lane][s] = o;
        }
    }
    __syncthreads();
    mm64t(xin, g_WT + 3*16384, b_out, pin, tid, false);
    __syncthreads();
    mm64t(pin, g_WT + 4*16384, rt_b1, qs, tid, true);
    __syncthreads();
    mm64t(qs, g_WT + 5*16384, rt_b2, ks, tid, false);
    __syncthreads();
    float* dst = g_rout[curBuf] + seq0*768;
    for (int i = tid; i < 2*6*128; i += 64) {
        int s = i / 768, r = i % 768;
        dst[(size_t)s*768 + r] = ((float*)ks)[r*2 + s];
    }
    // ---- fused predict head ----
    float* xv = (float*)qs;    // x: [2][256]
    float* hv = (float*)vs;    // h: [2][64]
    for (int c = tid; c < 128; c += 64) {
        #pragma unroll
        for (int s = 0; s < 2; s++) {
            float cent = ks[0][c][s];
            float sum = 0.f;
            #pragma unroll
            for (int l2 = 1; l2 < 6; l2++) sum += (ks[l2][c][s] - cent);
            xv[s*256 + c]       = sum * (1.0f / 5.0f);
            xv[s*256 + 128 + c] = cent;
        }
    }
    __syncthreads();
    #pragma unroll
    for (int s = 0; s < 2; s++) {
        int j = tid;
        float acc = pb1[j];
        const float4* wr = (const float4*)(pw1 + (size_t)j * 256);
        const float4* xr = (const float4*)(xv + s*256);
        #pragma unroll 8
        for (int j4 = 0; j4 < 64; j4++) {
            float4 wv = wr[j4];
            float4 x4 = xr[j4];
            acc += wv.x*x4.x + wv.y*x4.y + wv.z*x4.z + wv.w*x4.w;
        }
        hv[s*64 + j] = fmaxf(acc, 0.f);
    }
    __syncthreads();
    if (tid < 6) {
        int s = tid / 3, o = tid % 3;
        float acc = pb2[o];
        const float* wr = pw2 + o * 64;
        const float* hh = hv + s*64;
        #pragma unroll 8
        for (int j = 0; j < 64; j++) acc += wr[j] * hh[j];
        g_disp[(seq0 + s)*3 + o] = tanhf(acc);
    }
}

// ---------------- deterministic duplicate-aware scatter-add -----------------
__global__ void scatter_kernel(const int* __restrict__ start) {
    int gid = blockIdx.x * blockDim.x + threadIdx.x;
    if (gid >= NB*NM) return;
    int b = gid >> 9, m = gid & 511;
    int n = start[gid];
    const int* sb = start + b * NM;
    for (int j = 0; j < m; j++) if (sb[j] == n) return;
    float sx = 0.f, sy = 0.f, sz = 0.f;
    for (int j = m; j < NM; j++) {
        if (sb[j] == n) {
            const float* d = g_disp + (size_t)(b*NM + j) * 3;
            sx += d[0]; sy += d[1]; sz += d[2];
        }
    }
    float* p = g_pos4 + ((size_t)b*NN + n) * 4;
    p[0] += sx; p[1] += sy; p[2] += sz;
}

__global__ void finalize_kernel(float* __restrict__ out) {
    int i = blockIdx.x * blockDim.x + threadIdx.x;
    if (i < NB*NN) {
        out[i*3+0] = g_pos4[(size_t)i*4+0];
        out[i*3+1] = g_pos4[(size_t)i*4+1];
        out[i*3+2] = g_pos4[(size_t)i*4+2];
    }
}

// ---------------- host driver ----------------------------------------------
extern "C" void kernel_launch(void* const* d_in, const int* in_sizes, int n_in,
                              void* d_out, int out_size) {
    (void)in_sizes; (void)n_in; (void)out_size;
    const float* xyz      = (const float*)d_in[0];
    const int*   start    = (const int*)  d_in[1];
    const float* gumbel   = (const float*)d_in[2];
    const float* enc_w1   = (const float*)d_in[3];
    const float* enc_b1   = (const float*)d_in[4];
    const float* enc_w2   = (const float*)d_in[5];
    const float* enc_b2   = (const float*)d_in[6];
    const float* beta_w   = (const float*)d_in[7];
    const float* beta_b   = (const float*)d_in[8];
    const float* gamma_w  = (const float*)d_in[9];
    const float* gamma_b  = (const float*)d_in[10];
    const float* attn_w_in  = (const float*)d_in[11];
    const float* attn_b_in  = (const float*)d_in[12];
    const float* attn_w_out = (const float*)d_in[13];
    const float* attn_b_out = (const float*)d_in[14];
    const float* rt_w1    = (const float*)d_in[15];
    const float* rt_b1    = (const float*)d_in[16];
    const float* rt_w2    = (const float*)d_in[17];
    const float* rt_b2    = (const float*)d_in[18];
    const float* pred_w1  = (const float*)d_in[19];
    const float* pred_b1  = (const float*)d_in[20];
    const float* pred_w2  = (const float*)d_in[21];
    const float* pred_b2  = (const float*)d_in[22];

    cudaFuncSetAttribute(knn_step_kernel,
                         cudaFuncAttributeMaxDynamicSharedMemorySize, KNN_SMEM);

    transpose_kernel<<<512, 256>>>(attn_w_in, attn_w_out, rt_w1, rt_w2,
                                   beta_w, gamma_w);
    init_encode_kernel<<<NB*NN/4, 128>>>(xyz, enc_w1, enc_b1, enc_w2, enc_b2);
    proj_kernel<<<NB*NN/16, 128>>>(beta_b, gamma_b);

    for (int t = 0; t < NSTEPS; t++) {
        int cur = t & 1;
        int prv = (t == 0) ? -1 : (1 - cur);
        knn_step_kernel<<<NB*NM/KQPB, KTPB, KNN_SMEM>>>(start, gumbel, t);
        route_kernel<<<NB*NM/2, 64>>>(attn_b_in, attn_b_out, rt_b1, rt_b2,
                                      pred_w1, pred_b1, pred_w2, pred_b2, cur, prv);
        scatter_kernel<<<(NB*NM + 127)/128, 128>>>(start);
    }
    finalize_kernel<<<(NB*NN + 127)/128, 128>>>((float*)d_out);
}

// round 15
// speedup vs baseline: 1.3489x; 1.3489x over previous
#include <cuda_runtime.h>
#include <math_constants.h>

#define NB 4
#define NN 16384
#define NM 512
#define NC 128
#define NK 16
#define NL 6
#define NSTEPS 5

// ---------------- scratch (device globals: no allocations allowed) ----------
__device__ float g_feats[NB*NN*NC];
__device__ float g_Qf[NB*NN*NC];
__device__ float g_Gf[NB*NN*NC];
__device__ __align__(16) float g_pos4[NB*NN*4];
__device__ float g_wsel[NB*NM*NL*NC];
__device__ float g_rout[2][NB*NM*NL*NC];
__device__ float g_disp[NB*NM*3];

// ---------------- f32x2 packed helpers --------------------------------------
__device__ __forceinline__ void dfma2(unsigned long long& d,
                                      unsigned long long a,
                                      unsigned long long b) {
    asm("fma.rn.f32x2 %0, %1, %2, %0;" : "+l"(d) : "l"(a), "l"(b));
}
__device__ __forceinline__ unsigned long long dadd2(unsigned long long a,
                                                    unsigned long long b) {
    unsigned long long r;
    asm("add.rn.f32x2 %0, %1, %2;" : "=l"(r) : "l"(a), "l"(b));
    return r;
}
__device__ __forceinline__ unsigned long long dmul2(unsigned long long a,
                                                    unsigned long long b) {
    unsigned long long r;
    asm("mul.rn.f32x2 %0, %1, %2;" : "=l"(r) : "l"(a), "l"(b));
    return r;
}
__device__ __forceinline__ unsigned long long dfmar2(unsigned long long a,
                                                     unsigned long long b,
                                                     unsigned long long c) {
    unsigned long long r;
    asm("fma.rn.f32x2 %0, %1, %2, %3;" : "=l"(r) : "l"(a), "l"(b), "l"(c));
    return r;
}
__device__ __forceinline__ unsigned long long packdup(float w) {
    unsigned long long r;
    asm("mov.b64 %0, {%1, %1};" : "=l"(r) : "f"(w));
    return r;
}
__device__ __forceinline__ void unpack2(unsigned long long a, float& lo, float& hi) {
    asm("mov.b64 {%0, %1}, %2;" : "=f"(lo), "=f"(hi) : "l"(a));
}

// ---------------- fused init + encoder --------------------------------------
__global__ void init_encode_kernel(const float* __restrict__ xyz,
                                   const float* __restrict__ w1, const float* __restrict__ b1,
                                   const float* __restrict__ w2, const float* __restrict__ b2) {
    __shared__ float h[4][64];
    int tid = threadIdx.x;
    int p0 = blockIdx.x * 4;
    if (tid < 4) {
        const float* x = xyz + (size_t)(p0 + tid) * 3;
        *(float4*)&g_pos4[(size_t)(p0 + tid)*4] = make_float4(x[0], x[1], x[2], 0.f);
    }
    for (int i = tid; i < 4*64; i += 128) {
        int pt = i >> 6, j = i & 63;
        const float* x = xyz + (size_t)(p0 + pt) * 3;
        float v = b1[j] + w1[j*3+0]*x[0] + w1[j*3+1]*x[1] + w1[j*3+2]*x[2];
        h[pt][j] = fmaxf(v, 0.f);
    }
    __syncthreads();
    float acc[4];
    #pragma unroll
    for (int p = 0; p < 4; p++) acc[p] = b2[tid];
    const float4* wr = (const float4*)(w2 + (size_t)tid * 64);
    #pragma unroll
    for (int j4 = 0; j4 < 16; j4++) {
        float4 w = wr[j4];
        #pragma unroll
        for (int p = 0; p < 4; p++) {
            float4 hv = *(const float4*)&h[p][4*j4];
            acc[p] += w.x*hv.x + w.y*hv.y + w.z*hv.z + w.w*hv.w;
        }
    }
    #pragma unroll
    for (int p = 0; p < 4; p++)
        g_feats[(size_t)(p0 + p) * NC + tid] = acc[p];
}

// ---------------- beta/gamma projections (f32x2 point-pairs, R13-exact) -----
__global__ void proj_kernel(const float* __restrict__ bw, const float* __restrict__ bb,
                            const float* __restrict__ gw, const float* __restrict__ gb) {
    __shared__ __align__(8) float xs[128*16];      // xs[ch*16 + p]
    int c = threadIdx.x;                           // 128 threads
    size_t base = (size_t)blockIdx.x * 16 * 128;
    for (int i = c; i < 16*128; i += 128) {
        int p = i >> 7, ch = i & 127;
        xs[ch*16 + p] = g_feats[base + i];
    }
    __syncthreads();
    unsigned long long accQ[8], accG[8];
    unsigned long long bq = packdup(bb[c]), bg = packdup(gb[c]);
    #pragma unroll
    for (int p = 0; p < 8; p++) { accQ[p] = bq; accG[p] = bg; }
    const float4* wq = (const float4*)(bw + (size_t)c * 128);
    const float4* wg = (const float4*)(gw + (size_t)c * 128);
    for (int j4 = 0; j4 < 32; j4++) {
        float4 a = wq[j4];
        float4 g = wg[j4];
        float aa[4] = {a.x, a.y, a.z, a.w};
        float gg2[4] = {g.x, g.y, g.z, g.w};
        #pragma unroll
        for (int jj = 0; jj < 4; jj++) {
            int ch = 4*j4 + jj;
            unsigned long long wa = packdup(aa[jj]);
            unsigned long long wgv = packdup(gg2[jj]);
            const unsigned long long* x2 = (const unsigned long long*)&xs[ch*16];
            #pragma unroll
            for (int p = 0; p < 8; p++) {
                dfma2(accQ[p], x2[p], wa);
                dfma2(accG[p], x2[p], wgv);
            }
        }
    }
    #pragma unroll
    for (int p = 0; p < 8; p++) {
        float q0, q1, g0, g1;
        unpack2(accQ[p], q0, q1);
        unpack2(accG[p], g0, g1);
        g_Qf[base + (size_t)(2*p)*128 + c]   = q0;
        g_Qf[base + (size_t)(2*p+1)*128 + c] = q1;
        g_Gf[base + (size_t)(2*p)*128 + c]   = g0;
        g_Gf[base + (size_t)(2*p+1)*128 + c] = g1;
    }
}

// ---------------- KNN: warp-distributed sorted top-17 insert ----------------
__device__ __forceinline__ void kinsert(unsigned bal, float d, int ci,
                                        float& ld, int& li, float& tau, int lane) {
    do {
        int src = __ffs(bal) - 1; bal &= bal - 1;
        float dc = __shfl_sync(0xffffffffu, d, src);
        int   ic = __shfl_sync(0xffffffffu, ci, src);
        float pd = __shfl_up_sync(0xffffffffu, ld, 1);
        int   pi = __shfl_up_sync(0xffffffffu, li, 1);
        unsigned lt = __ballot_sync(0xffffffffu,
                (ld < dc) || ((ld == dc) && (li < ic))) & 0x1FFFFu;
        int pn = __popc(lt);
        if (lane < 17) {
            if (lane == pn)      { ld = dc; li = ic; }
            else if (lane > pn)  { ld = pd; li = pi; }
        }
    } while (bal);
    tau = __shfl_sync(0xffffffffu, ld, 16);
}

// ---------------- fused per-step selector, positions resident in smem ------
#define KTPB 512
#define KQPB 16
#define KNN_SMEM (3*NN*4)

__global__ __launch_bounds__(KTPB)
void knn_step_kernel(const int* __restrict__ start,
                     const float* __restrict__ gumbel, int t) {
    extern __shared__ __align__(8) float sm[];
    float* sx = sm;
    float* sy = sm + NN;
    float* sz = sm + 2*NN;
    int tid = threadIdx.x, warp = tid >> 5, lane = tid & 31;
    int b = blockIdx.x / (NM/KQPB);             // 32 blocks per batch
    int m = (blockIdx.x % (NM/KQPB)) * KQPB + warp;
    int gw = b*NM + m;
    int qidx = start[gw];
    const float4* pos = (const float4*)(g_pos4 + (size_t)b*NN*4);
    const float* Gf = g_Gf + (size_t)b*NN*NC;

    for (int i = tid; i < NN; i += KTPB) {
        float4 p = pos[i];
        sx[i] = p.x; sy[i] = p.y; sz[i] = p.z;
    }
    {   // walk[0] = feats[start]
        const float* fr = g_feats + ((size_t)b*NN + qidx) * NC;
        float* wr = g_wsel + (size_t)gw * NL * NC;
        #pragma unroll
        for (int r = 0; r < 4; r++) wr[lane + 32*r] = fr[lane + 32*r];
    }
    __syncthreads();

    const unsigned long long* sx2 = (const unsigned long long*)sx;
    const unsigned long long* sy2 = (const unsigned long long*)sy;
    const unsigned long long* sz2 = (const unsigned long long*)sz;

    for (int l = 0; l < NL-1; l++) {
        float qx = sx[qidx], qy = sy[qidx], qz = sz[qidx];
        unsigned long long nqx = packdup(-qx);
        unsigned long long nqy = packdup(-qy);
        unsigned long long nqz = packdup(-qz);
        float ld = CUDART_INF_F;
        int   li = 0x7FFFFFFF;
        float tau = CUDART_INF_F;

        for (int pi = lane; pi < NN/2; pi += 32) {
            unsigned long long dxp = dadd2(sx2[pi], nqx);
            unsigned long long dyp = dadd2(sy2[pi], nqy);
            unsigned long long dzp = dadd2(sz2[pi], nqz);
            unsigned long long dp = dmul2(dxp, dxp);
            dp = dfmar2(dyp, dyp, dp);
            dp = dfmar2(dzp, dzp, dp);       // dz*dz + (dy*dy + dx*dx), per-lane IEEE
            float d0, d1;
            unpack2(dp, d0, d1);
            int c0 = 2*pi;
            unsigned bal0 = __ballot_sync(0xffffffffu, d0 < tau);
            if (bal0) kinsert(bal0, d0, c0, ld, li, tau, lane);
            unsigned bal1 = __ballot_sync(0xffffffffu, d1 < tau);
            if (bal1) kinsert(bal1, d1, c0 + 1, ld, li, tau, lane);
        }

        int nb = __shfl_sync(0xffffffffu, li, lane < 31 ? lane + 1 : 31);
        const float* Q = g_Qf + ((size_t)b*NN + qidx) * NC;
        float qv0 = Q[lane], qv1 = Q[lane+32], qv2 = Q[lane+64], qv3 = Q[lane+96];
        float pk[16];
        #pragma unroll
        for (int k = 0; k < 16; k++) {
            int nk = __shfl_sync(0xffffffffu, nb, k);   // li of lane k+1
            const float* gr = Gf + (size_t)nk * NC;
            pk[k] = qv0*gr[lane] + qv1*gr[lane+32] + qv2*gr[lane+64] + qv3*gr[lane+96];
        }
        #pragma unroll
        for (int k = 0; k < 16; k++) {
            #pragma unroll
            for (int off = 16; off; off >>= 1)
                pk[k] += __shfl_xor_sync(0xffffffffu, pk[k], off);
        }
        const float* gm = gumbel + ((((size_t)t*(NL-1) + l)*NB + b)*NM + m) * NK;
        float best = -CUDART_INF_F; int bk = 0;
        #pragma unroll
        for (int k = 0; k < 16; k++) {
            float s = pk[k] / 11.313708498984761f + gm[k];   // /sqrt(128)
            if (s > best) { best = s; bk = k; }
        }
        qidx = __shfl_sync(0xffffffffu, li, bk + 1);
        const float* fr = g_feats + ((size_t)b*NN + qidx) * NC;
        float* wr = g_wsel + ((size_t)gw * NL + (l + 1)) * NC;
        #pragma unroll
        for (int r = 0; r < 4; r++) wr[lane + 32*r] = fr[lane + 32*r];
    }
}

// ---------------- route matmul: weights staged through shared memory --------
// Thread t computes channels 2t, 2t+1 for both sequences. Weights loaded in
// four 32-column chunks: coalesced float4 global loads (high MLP) into padded
// smem [32][129] (conflict-free stores), then LDS reads during compute.
// Accumulation order = ascending j, one fma per j per channel (bit-identical).
#define WPAD 129

__device__ __forceinline__ void mmS(const float (*in)[128][2],
                                    const float* __restrict__ W,
                                    const float* __restrict__ bias,
                                    float (*out)[128][2],
                                    float* __restrict__ Wsm,
                                    int tid, bool doRelu) {
    int c0 = 2*tid;
    unsigned long long acc0[6], acc1[6];
    unsigned long long b0 = packdup(bias[c0]), b1 = packdup(bias[c0 + 1]);
    #pragma unroll
    for (int i = 0; i < 6; i++) { acc0[i] = b0; acc1[i] = b1; }
    const unsigned long long* inu = (const unsigned long long*)in;
    const float4* W4 = (const float4*)W;           // row stride = 32 float4
    #pragma unroll 1
    for (int ch = 0; ch < 4; ch++) {
        int j0 = ch * 32;
        __syncthreads();                           // protect Wsm reuse
        for (int g = tid; g < 1024; g += 64) {     // 32j x 128c = 1024 float4
            int c = g >> 3, s = g & 7;
            float4 v = __ldg(&W4[c*32 + (j0 >> 2) + s]);
            Wsm[(4*s + 0)*WPAD + c] = v.x;
            Wsm[(4*s + 1)*WPAD + c] = v.y;
            Wsm[(4*s + 2)*WPAD + c] = v.z;
            Wsm[(4*s + 3)*WPAD + c] = v.w;
        }
        __syncthreads();
        #pragma unroll 8
        for (int jj = 0; jj < 32; jj++) {
            int j = j0 + jj;
            unsigned long long w0 = packdup(Wsm[jj*WPAD + c0]);
            unsigned long long w1 = packdup(Wsm[jj*WPAD + c0 + 1]);
            #pragma unroll
            for (int l2 = 0; l2 < 6; l2++) {
                unsigned long long r = inu[l2*128 + j];
                dfma2(acc0[l2], r, w0);
                dfma2(acc1[l2], r, w1);
            }
        }
    }
    #pragma unroll
    for (int l2 = 0; l2 < 6; l2++) {
        float v0, v1, u0, u1;
        unpack2(acc0[l2], v0, v1);
        unpack2(acc1[l2], u0, u1);
        if (doRelu) {
            v0 = fmaxf(v0, 0.f); v1 = fmaxf(v1, 0.f);
            u0 = fmaxf(u0, 0.f); u1 = fmaxf(u1, 0.f);
        }
        out[l2][c0][0] = v0;     out[l2][c0][1] = v1;
        out[l2][c0+1][0] = u0;   out[l2][c0+1][1] = u1;
    }
}

__global__ void route_kernel(const float* __restrict__ w_in, const float* __restrict__ b_in,
                             const float* __restrict__ w_out, const float* __restrict__ b_out,
                             const float* __restrict__ rt_w1, const float* __restrict__ rt_b1,
                             const float* __restrict__ rt_w2, const float* __restrict__ rt_b2,
                             const float* __restrict__ pw1, const float* __restrict__ pb1,
                             const float* __restrict__ pw2, const float* __restrict__ pb2,
                             int curBuf, int prevBuf) {
    __shared__ __align__(16) float xin[6][128][2];
    __shared__ __align__(16) float pin[6][128][2];
    __shared__ __align__(16) float qs[6][128][2];
    __shared__ __align__(16) float ks[6][128][2];
    __shared__ __align__(16) float vs[6][128][2];
    __shared__ float sc[2][4][6][6];
    __shared__ __align__(16) float Wsm[32*WPAD];
    int tid = threadIdx.x;                      // 64 threads
    size_t seq0 = (size_t)blockIdx.x * 2;
    const float* curr = g_wsel;
    const float* prev = (prevBuf < 0) ? g_wsel : g_rout[prevBuf];
    for (int i = tid; i < 2*6*128; i += 64) {
        int s = i / 768, r = i % 768;
        ((float*)xin)[r*2 + s] = curr[(seq0 + s)*768 + r];
        ((float*)pin)[r*2 + s] = prev[(seq0 + s)*768 + r];
    }
    __syncthreads();
    mmS(xin, w_in,            b_in,        qs, Wsm, tid, false);   // wq
    mmS(pin, w_in + 128*128,  b_in + 128,  ks, Wsm, tid, false);   // wk
    mmS(pin, w_in + 256*128,  b_in + 256,  vs, Wsm, tid, false);   // wv
    __syncthreads();
    int warp = tid >> 5, lane = tid & 31;
    for (int pp = warp; pp < 8; pp += 2) {
        int s = pp >> 2, h = pp & 3;
        for (int e = lane; e < 36; e += 32) {
            int lq = e / 6, lk = e % 6;
            float d = 0.f;
            #pragma unroll
            for (int dd = 0; dd < 32; dd++)
                d += qs[lq][h*32 + dd][s] * ks[lk][h*32 + dd][s];
            sc[s][h][lq][lk] = d / 5.656854249492381f;
        }
        __syncwarp();
        if (lane < 6) {
            float mx = -CUDART_INF_F;
            #pragma unroll
            for (int j = 0; j < 6; j++) mx = fmaxf(mx, sc[s][h][lane][j]);
            float ex[6]; float sum = 0.f;
            #pragma unroll
            for (int j = 0; j < 6; j++) { ex[j] = expf(sc[s][h][lane][j] - mx); sum += ex[j]; }
            #pragma unroll
            for (int j = 0; j < 6; j++) sc[s][h][lane][j] = ex[j] / sum;
        }
        __syncwarp();
        for (int lq = 0; lq < 6; lq++) {
            float o = 0.f;
            #pragma unroll
            for (int j = 0; j < 6; j++) o += sc[s][h][lq][j] * vs[j][h*32 + lane][s];
            xin[lq][h*32 + lane][s] = o;
        }
    }
    __syncthreads();
    mmS(xin, w_out, b_out, pin, Wsm, tid, false);
    __syncthreads();
    mmS(pin, rt_w1, rt_b1, qs, Wsm, tid, true);
    __syncthreads();
    mmS(qs, rt_w2, rt_b2, ks, Wsm, tid, false);
    __syncthreads();
    float* dst = g_rout[curBuf] + seq0*768;
    for (int i = tid; i < 2*6*128; i += 64) {
        int s = i / 768, r = i % 768;
        dst[(size_t)s*768 + r] = ((float*)ks)[r*2 + s];
    }
    // ---- fused predict head ----
    float* xv = (float*)qs;    // x: [2][256]
    float* hv = (float*)vs;    // h: [2][64]
    for (int c = tid; c < 128; c += 64) {
        #pragma unroll
        for (int s = 0; s < 2; s++) {
            float cent = ks[0][c][s];
            float sum = 0.f;
            #pragma unroll
            for (int l2 = 1; l2 < 6; l2++) sum += (ks[l2][c][s] - cent);
            xv[s*256 + c]       = sum * (1.0f / 5.0f);
            xv[s*256 + 128 + c] = cent;
        }
    }
    __syncthreads();
    #pragma unroll
    for (int s = 0; s < 2; s++) {
        int j = tid;
        float acc = pb1[j];
        const float4* wr = (const float4*)(pw1 + (size_t)j * 256);
        const float4* xr = (const float4*)(xv + s*256);
        #pragma unroll 8
        for (int j4 = 0; j4 < 64; j4++) {
            float4 wv = wr[j4];
            float4 x4 = xr[j4];
            acc += wv.x*x4.x + wv.y*x4.y + wv.z*x4.z + wv.w*x4.w;
        }
        hv[s*64 + j] = fmaxf(acc, 0.f);
    }
    __syncthreads();
    if (tid < 6) {
        int s = tid / 3, o = tid % 3;
        float acc = pb2[o];
        const float* wr = pw2 + o * 64;
        const float* hh = hv + s*64;
        #pragma unroll 8
        for (int j = 0; j < 64; j++) acc += wr[j] * hh[j];
        g_disp[(seq0 + s)*3 + o] = tanhf(acc);
    }
}

// ---------------- deterministic duplicate-aware scatter-add -----------------
__global__ void scatter_kernel(const int* __restrict__ start) {
    int gid = blockIdx.x * blockDim.x + threadIdx.x;
    if (gid >= NB*NM) return;
    int b = gid >> 9, m = gid & 511;
    int n = start[gid];
    const int* sb = start + b * NM;
    for (int j = 0; j < m; j++) if (sb[j] == n) return;
    float sx = 0.f, sy = 0.f, sz = 0.f;
    for (int j = m; j < NM; j++) {
        if (sb[j] == n) {
            const float* d = g_disp + (size_t)(b*NM + j) * 3;
            sx += d[0]; sy += d[1]; sz += d[2];
        }
    }
    float* p = g_pos4 + ((size_t)b*NN + n) * 4;
    p[0] += sx; p[1] += sy; p[2] += sz;
}

__global__ void finalize_kernel(float* __restrict__ out) {
    int i = blockIdx.x * blockDim.x + threadIdx.x;
    if (i < NB*NN) {
        out[i*3+0] = g_pos4[(size_t)i*4+0];
        out[i*3+1] = g_pos4[(size_t)i*4+1];
        out[i*3+2] = g_pos4[(size_t)i*4+2];
    }
}

// ---------------- host driver ----------------------------------------------
extern "C" void kernel_launch(void* const* d_in, const int* in_sizes, int n_in,
                              void* d_out, int out_size) {
    (void)in_sizes; (void)n_in; (void)out_size;
    const float* xyz      = (const float*)d_in[0];
    const int*   start    = (const int*)  d_in[1];
    const float* gumbel   = (const float*)d_in[2];
    const float* enc_w1   = (const float*)d_in[3];
    const float* enc_b1   = (const float*)d_in[4];
    const float* enc_w2   = (const float*)d_in[5];
    const float* enc_b2   = (const float*)d_in[6];
    const float* beta_w   = (const float*)d_in[7];
    const float* beta_b   = (const float*)d_in[8];
    const float* gamma_w  = (const float*)d_in[9];
    const float* gamma_b  = (const float*)d_in[10];
    const float* attn_w_in  = (const float*)d_in[11];
    const float* attn_b_in  = (const float*)d_in[12];
    const float* attn_w_out = (const float*)d_in[13];
    const float* attn_b_out = (const float*)d_in[14];
    const float* rt_w1    = (const float*)d_in[15];
    const float* rt_b1    = (const float*)d_in[16];
    const float* rt_w2    = (const float*)d_in[17];
    const float* rt_b2    = (const float*)d_in[18];
    const float* pred_w1  = (const float*)d_in[19];
    const float* pred_b1  = (const float*)d_in[20];
    const float* pred_w2  = (const float*)d_in[21];
    const float* pred_b2  = (const float*)d_in[22];

    cudaFuncSetAttribute(knn_step_kernel,
                         cudaFuncAttributeMaxDynamicSharedMemorySize, KNN_SMEM);

    init_encode_kernel<<<NB*NN/4, 128>>>(xyz, enc_w1, enc_b1, enc_w2, enc_b2);
    proj_kernel<<<NB*NN/16, 128>>>(beta_w, beta_b, gamma_w, gamma_b);

    for (int t = 0; t < NSTEPS; t++) {
        int cur = t & 1;
        int prv = (t == 0) ? -1 : (1 - cur);
        knn_step_kernel<<<NB*NM/KQPB, KTPB, KNN_SMEM>>>(start, gumbel, t);
        route_kernel<<<NB*NM/2, 64>>>(attn_w_in, attn_b_in, attn_w_out, attn_b_out,
                                      rt_w1, rt_b1, rt_w2, rt_b2,
                                      pred_w1, pred_b1, pred_w2, pred_b2, cur, prv);
        scatter_kernel<<<(NB*NM + 127)/128, 128>>>(start);
    }
    finalize_kernel<<<(NB*NN + 127)/128, 128>>>((float*)d_out);
}